// round 1
// baseline (speedup 1.0000x reference)
#include <cuda_runtime.h>
#include <math.h>

// ---------------------------------------------------------------------------
// GNNLoss: focal loss + accuracy over edges (E=12.8M) and nodes (N=200K).
// Key idea: per-node 16-bit key = (pi==0) ? 0 : (batch<<10)|pi  (batch<16,
// pi<1000). Edge target = (key[src]==key[dst]) && key[src]!=0.
// Output: [loss, edge_loss, node_loss, edge_acc, node_acc] (5 floats).
// ---------------------------------------------------------------------------

#define MAX_NODES 262144

__device__ unsigned short g_keys[MAX_NODES];
__device__ double        g_loss_sum[2];   // [0]=edge, [1]=node
__device__ unsigned int  g_acc_cnt[2];    // [0]=edge, [1]=node

__global__ void init_kernel() {
    g_loss_sum[0] = 0.0;
    g_loss_sum[1] = 0.0;
    g_acc_cnt[0]  = 0u;
    g_acc_cnt[1]  = 0u;
}

// focal term: alpha_t * ce * (1-p_t)^2, torchvision sigmoid_focal_loss element
__device__ __forceinline__ float focal_term(float x, bool t) {
    float a   = fabsf(x);
    float em  = __expf(-a);              // exp(-|x|)
    float inv = __frcp_rn(1.0f + em);
    float p   = (x >= 0.0f) ? inv : em * inv;   // sigmoid(x)
    float ce  = fmaxf(x, 0.0f) - (t ? x : 0.0f) + log1pf(em);
    float omp = t ? (1.0f - p) : p;      // 1 - p_t
    float at  = t ? 0.25f : 0.75f;       // alpha_t (ALPHA=0.25)
    return at * ce * omp * omp;
}

// block-level reduction of (float sum, int count) -> one atomicAdd each
__device__ __forceinline__ void block_reduce_commit(float s, int c, int which) {
    // warp reduce
    #pragma unroll
    for (int o = 16; o > 0; o >>= 1) {
        s += __shfl_down_sync(0xFFFFFFFFu, s, o);
        c += __shfl_down_sync(0xFFFFFFFFu, c, o);
    }
    __shared__ float sh_s[32];
    __shared__ int   sh_c[32];
    int lane = threadIdx.x & 31;
    int wid  = threadIdx.x >> 5;
    if (lane == 0) { sh_s[wid] = s; sh_c[wid] = c; }
    __syncthreads();
    int nw = (blockDim.x + 31) >> 5;
    if (wid == 0) {
        s = (lane < nw) ? sh_s[lane] : 0.0f;
        c = (lane < nw) ? sh_c[lane] : 0;
        #pragma unroll
        for (int o = 16; o > 0; o >>= 1) {
            s += __shfl_down_sync(0xFFFFFFFFu, s, o);
            c += __shfl_down_sync(0xFFFFFFFFu, c, o);
        }
        if (lane == 0) {
            atomicAdd(&g_loss_sum[which], (double)s);
            atomicAdd(&g_acc_cnt[which], (unsigned int)c);
        }
    }
}

// Node pass: build keys, accumulate node focal loss + accuracy
__global__ void node_kernel(const float* __restrict__ node_logits,
                            const int*   __restrict__ batch,
                            const int*   __restrict__ pinst,
                            int n) {
    int i = blockIdx.x * blockDim.x + threadIdx.x;
    float s = 0.0f;
    int   c = 0;
    if (i < n) {
        int p = pinst[i];
        int b = batch[i];
        unsigned short key = (p == 0) ? (unsigned short)0
                                      : (unsigned short)((b << 10) | p);
        g_keys[i] = key;
        float x = node_logits[i];
        bool  t = (p != 0);
        s = focal_term(x, t);
        c = ((x > 0.0f) == t) ? 1 : 0;
    }
    block_reduce_commit(s, c, 1);
}

// Edge pass: vec4 streamed loads + 2 random key gathers per edge
__global__ void edge_kernel(const float4* __restrict__ el,
                            const int4*   __restrict__ srcv,
                            const int4*   __restrict__ dstv,
                            int nvec) {
    int i = blockIdx.x * blockDim.x + threadIdx.x;
    float s = 0.0f;
    int   c = 0;
    if (i < nvec) {
        float4 x  = el[i];
        int4   sv = srcv[i];
        int4   dv = dstv[i];

        unsigned short ks0 = __ldg(&g_keys[sv.x]);
        unsigned short ks1 = __ldg(&g_keys[sv.y]);
        unsigned short ks2 = __ldg(&g_keys[sv.z]);
        unsigned short ks3 = __ldg(&g_keys[sv.w]);
        unsigned short kd0 = __ldg(&g_keys[dv.x]);
        unsigned short kd1 = __ldg(&g_keys[dv.y]);
        unsigned short kd2 = __ldg(&g_keys[dv.z]);
        unsigned short kd3 = __ldg(&g_keys[dv.w]);

        bool t0 = (ks0 == kd0) && (ks0 != 0);
        bool t1 = (ks1 == kd1) && (ks1 != 0);
        bool t2 = (ks2 == kd2) && (ks2 != 0);
        bool t3 = (ks3 == kd3) && (ks3 != 0);

        s  = focal_term(x.x, t0);
        s += focal_term(x.y, t1);
        s += focal_term(x.z, t2);
        s += focal_term(x.w, t3);

        c  = ((x.x > 0.0f) == t0) ? 1 : 0;
        c += ((x.y > 0.0f) == t1) ? 1 : 0;
        c += ((x.z > 0.0f) == t2) ? 1 : 0;
        c += ((x.w > 0.0f) == t3) ? 1 : 0;
    }
    block_reduce_commit(s, c, 0);
}

// Finalize: handle edge tail (E % 4), compute the 5 outputs
__global__ void finalize_kernel(const float* __restrict__ el,
                                const int*   __restrict__ src,
                                const int*   __restrict__ dst,
                                int E, int N, int tail_start,
                                float* __restrict__ out) {
    if (threadIdx.x == 0 && blockIdx.x == 0) {
        double es = g_loss_sum[0];
        double ns = g_loss_sum[1];
        unsigned int ec = g_acc_cnt[0];
        unsigned int nc = g_acc_cnt[1];
        for (int e = tail_start; e < E; e++) {
            int sidx = src[e], didx = dst[e];
            unsigned short ks = g_keys[sidx], kd = g_keys[didx];
            bool t = (ks == kd) && (ks != 0);
            float x = el[e];
            es += (double)focal_term(x, t);
            ec += ((x > 0.0f) == t) ? 1u : 0u;
        }
        float edge_loss = (float)(es / (double)E);
        float node_loss = (float)(ns / (double)N);
        float edge_acc  = (float)((double)ec / (double)E);
        float node_acc  = (float)((double)nc / (double)N);
        out[0] = edge_loss + node_loss;  // EDGE_W=NODE_W=1
        out[1] = edge_loss;
        out[2] = node_loss;
        out[3] = edge_acc;
        out[4] = node_acc;
    }
}

extern "C" void kernel_launch(void* const* d_in, const int* in_sizes, int n_in,
                              void* d_out, int out_size) {
    const float* edge_logits = (const float*)d_in[0];
    const float* node_logits = (const float*)d_in[1];
    const int*   batch       = (const int*)d_in[2];
    const int*   pinst       = (const int*)d_in[3];
    const int*   edge_index  = (const int*)d_in[4];

    int E = in_sizes[0];
    int N = in_sizes[1];
    const int* src = edge_index;
    const int* dst = edge_index + E;

    float* out = (float*)d_out;

    init_kernel<<<1, 1>>>();

    int nthreads = 256;
    int nblocks_n = (N + nthreads - 1) / nthreads;
    node_kernel<<<nblocks_n, nthreads>>>(node_logits, batch, pinst, N);

    int nvec = E >> 2;  // E=12.8M divisible by 4; tail handled in finalize
    int nblocks_e = (nvec + nthreads - 1) / nthreads;
    edge_kernel<<<nblocks_e, nthreads>>>((const float4*)edge_logits,
                                         (const int4*)src,
                                         (const int4*)dst, nvec);

    finalize_kernel<<<1, 32>>>(edge_logits, src, dst, E, N, nvec << 2, out);
}

// round 2
// speedup vs baseline: 1.5649x; 1.5649x over previous
#include <cuda_runtime.h>
#include <math.h>

// ---------------------------------------------------------------------------
// GNNLoss: focal loss + accuracy over edges (E=12.8M) and nodes (N=200K).
//
// R2 strategy: the R1 kernel was exactly on the L1tex-wavefront roofline
// (25.6M divergent lane-LDGs ~= 86us). Replace the random global gathers with
// shared-memory gathers: an 8-bit per-node filter table (200KB, fits smem)
// resolves ~99.6% of edges; the rest (hash-equal, ~0.4%) take a predicated
// exact u16 global gather. Exact result, no approximation.
//
// key[node]  = (pi==0) ? 0 : (batch<<10)|pi     (u16 exact; batch<16, pi<1000)
// hash[node] = (key==0) ? 0 : (key % 255) + 1   (u8; 0 reserved for key==0)
// target     = hash_s!=hash_d -> false
//              hash_s==hash_d==0 -> false
//              else -> (key_s == key_d)   [rare exact check]
// ---------------------------------------------------------------------------

#define MAX_NODES 262144

__device__ __align__(16) unsigned short g_keys[MAX_NODES];
__device__ __align__(16) unsigned char  g_hash[MAX_NODES];
__device__ double        g_loss_sum[2];   // [0]=edge, [1]=node
__device__ unsigned int  g_acc_cnt[2];    // [0]=edge, [1]=node

__global__ void init_kernel() {
    g_loss_sum[0] = 0.0;
    g_loss_sum[1] = 0.0;
    g_acc_cnt[0]  = 0u;
    g_acc_cnt[1]  = 0u;
}

// focal term: alpha_t * ce * (1-p_t)^gamma, torchvision sigmoid_focal_loss
__device__ __forceinline__ float focal_term(float x, bool t) {
    float a   = fabsf(x);
    float em  = __expf(-a);                     // exp(-|x|)
    float inv = __frcp_rn(1.0f + em);
    float p   = (x >= 0.0f) ? inv : em * inv;   // sigmoid(x)
    float ce  = fmaxf(x, 0.0f) - (t ? x : 0.0f) + log1pf(em);
    float omp = t ? (1.0f - p) : p;             // 1 - p_t
    float at  = t ? 0.25f : 0.75f;              // alpha_t (ALPHA=0.25)
    return at * ce * omp * omp;
}

// block-level reduction of (float sum, int count) -> one atomicAdd each
__device__ __forceinline__ void block_reduce_commit(float s, int c, int which) {
    #pragma unroll
    for (int o = 16; o > 0; o >>= 1) {
        s += __shfl_down_sync(0xFFFFFFFFu, s, o);
        c += __shfl_down_sync(0xFFFFFFFFu, c, o);
    }
    __shared__ float sh_s[32];
    __shared__ int   sh_c[32];
    int lane = threadIdx.x & 31;
    int wid  = threadIdx.x >> 5;
    if (lane == 0) { sh_s[wid] = s; sh_c[wid] = c; }
    __syncthreads();
    int nw = (blockDim.x + 31) >> 5;
    if (wid == 0) {
        s = (lane < nw) ? sh_s[lane] : 0.0f;
        c = (lane < nw) ? sh_c[lane] : 0;
        #pragma unroll
        for (int o = 16; o > 0; o >>= 1) {
            s += __shfl_down_sync(0xFFFFFFFFu, s, o);
            c += __shfl_down_sync(0xFFFFFFFFu, c, o);
        }
        if (lane == 0) {
            atomicAdd(&g_loss_sum[which], (double)s);
            atomicAdd(&g_acc_cnt[which], (unsigned int)c);
        }
    }
}

// Node pass: build key + hash tables, accumulate node focal loss + accuracy
__global__ void node_kernel(const float* __restrict__ node_logits,
                            const int*   __restrict__ batch,
                            const int*   __restrict__ pinst,
                            int n) {
    int i = blockIdx.x * blockDim.x + threadIdx.x;
    float s = 0.0f;
    int   c = 0;
    if (i < n) {
        int p = pinst[i];
        int b = batch[i];
        unsigned short key = (p == 0) ? (unsigned short)0
                                      : (unsigned short)((b << 10) | p);
        g_keys[i] = key;
        g_hash[i] = (key == 0) ? (unsigned char)0
                               : (unsigned char)((key % 255) + 1);
        float x = node_logits[i];
        bool  t = (p != 0);
        s = focal_term(x, t);
        c = ((x > 0.0f) == t) ? 1 : 0;
    }
    block_reduce_commit(s, c, 1);
}

__device__ __forceinline__ bool edge_target(const unsigned char* sh,
                                            int sidx, int didx) {
    unsigned int hs = sh[sidx];
    unsigned int hd = sh[didx];
    bool t = false;
    if ((hs == hd) & (hs != 0u)) {          // ~0.4% of edges
        t = (g_keys[sidx] == g_keys[didx]); // predicated exact LDGs
    }
    return t;
}

// Edge pass: persistent blocks, 200KB hash table in smem, LDS gathers
__global__ void __launch_bounds__(1024, 1)
edge_kernel(const float4* __restrict__ el,
            const int4*   __restrict__ srcv,
            const int4*   __restrict__ dstv,
            int nvec, int n) {
    extern __shared__ unsigned char sh[];

    // broadcast-load the hash table into shared memory (vectorized)
    int nw = (n + 15) >> 4;  // uint4 words; g_hash is padded to MAX_NODES
    const uint4* hv = (const uint4*)g_hash;
    uint4* sv4 = (uint4*)sh;
    for (int i = threadIdx.x; i < nw; i += blockDim.x) sv4[i] = hv[i];
    __syncthreads();

    float s = 0.0f;
    int   c = 0;
    int stride = gridDim.x * blockDim.x;
    for (int i = blockIdx.x * blockDim.x + threadIdx.x; i < nvec; i += stride) {
        float4 x  = __ldcs(&el[i]);      // streaming: don't pollute tiny L1
        int4   sv = __ldcs(&srcv[i]);
        int4   dv = __ldcs(&dstv[i]);

        bool t0 = edge_target(sh, sv.x, dv.x);
        bool t1 = edge_target(sh, sv.y, dv.y);
        bool t2 = edge_target(sh, sv.z, dv.z);
        bool t3 = edge_target(sh, sv.w, dv.w);

        s += focal_term(x.x, t0);
        s += focal_term(x.y, t1);
        s += focal_term(x.z, t2);
        s += focal_term(x.w, t3);

        c += ((x.x > 0.0f) == t0) ? 1 : 0;
        c += ((x.y > 0.0f) == t1) ? 1 : 0;
        c += ((x.z > 0.0f) == t2) ? 1 : 0;
        c += ((x.w > 0.0f) == t3) ? 1 : 0;
    }
    block_reduce_commit(s, c, 0);
}

// Finalize: edge tail (E % 4, exact via g_keys) + compute the 5 outputs
__global__ void finalize_kernel(const float* __restrict__ el,
                                const int*   __restrict__ src,
                                const int*   __restrict__ dst,
                                int E, int N, int tail_start,
                                float* __restrict__ out) {
    if (threadIdx.x == 0 && blockIdx.x == 0) {
        double es = g_loss_sum[0];
        double ns = g_loss_sum[1];
        unsigned int ec = g_acc_cnt[0];
        unsigned int nc = g_acc_cnt[1];
        for (int e = tail_start; e < E; e++) {
            int sidx = src[e], didx = dst[e];
            unsigned short ks = g_keys[sidx], kd = g_keys[didx];
            bool t = (ks == kd) && (ks != 0);
            float x = el[e];
            es += (double)focal_term(x, t);
            ec += ((x > 0.0f) == t) ? 1u : 0u;
        }
        float edge_loss = (float)(es / (double)E);
        float node_loss = (float)(ns / (double)N);
        float edge_acc  = (float)((double)ec / (double)E);
        float node_acc  = (float)((double)nc / (double)N);
        out[0] = edge_loss + node_loss;  // EDGE_W=NODE_W=1
        out[1] = edge_loss;
        out[2] = node_loss;
        out[3] = edge_acc;
        out[4] = node_acc;
    }
}

extern "C" void kernel_launch(void* const* d_in, const int* in_sizes, int n_in,
                              void* d_out, int out_size) {
    const float* edge_logits = (const float*)d_in[0];
    const float* node_logits = (const float*)d_in[1];
    const int*   batch       = (const int*)d_in[2];
    const int*   pinst       = (const int*)d_in[3];
    const int*   edge_index  = (const int*)d_in[4];

    int E = in_sizes[0];
    int N = in_sizes[1];
    const int* src = edge_index;
    const int* dst = edge_index + E;

    float* out = (float*)d_out;

    // dynamic smem for the 200KB hash table (needs opt-in above 48KB)
    int smem_bytes = ((N + 15) >> 4) << 4;
    cudaFuncSetAttribute(edge_kernel,
                         cudaFuncAttributeMaxDynamicSharedMemorySize,
                         smem_bytes);

    int sm_count = 148;
    cudaDeviceGetAttribute(&sm_count, cudaDevAttrMultiProcessorCount, 0);

    init_kernel<<<1, 1>>>();

    int nthreads = 256;
    int nblocks_n = (N + nthreads - 1) / nthreads;
    node_kernel<<<nblocks_n, nthreads>>>(node_logits, batch, pinst, N);

    int nvec = E >> 2;  // tail handled in finalize
    edge_kernel<<<sm_count, 1024, smem_bytes>>>((const float4*)edge_logits,
                                                (const int4*)src,
                                                (const int4*)dst, nvec, N);

    finalize_kernel<<<1, 32>>>(edge_logits, src, dst, E, N, nvec << 2, out);
}

// round 3
// speedup vs baseline: 1.9045x; 1.2170x over previous
#include <cuda_runtime.h>
#include <math.h>

// ---------------------------------------------------------------------------
// GNNLoss fused single-kernel (R3).
// key[node]  = (pi==0) ? 0 : (batch<<10)|pi     (u16 exact; batch<16, pi<1000)
// hash[node] = (key==0) ? 0 : (key % 255) + 1   (u8 filter, 200KB, in smem)
// target     = hash mismatch -> false; hash==hash==0 -> false;
//              else exact u16 key compare (~0.4% of edges, predicated LDG).
//
// Persistent grid (1 CTA/SM, co-resident by smem limit) with software grid
// barriers: phase1 nodes -> barrier -> phase2 edges -> barrier -> block0
// reduces partials and writes [loss, edge_loss, node_loss, edge_acc, node_acc].
//
// Focal math (exact algebraic rewrite, 2 MUFU + ~15 FFMA per element):
//   a=|x|, em=e^-a, L=log(1+em), q=em/(1+em) (Newton recip, no MUFU)
//   match=(x>=0)==t:  ce = match? L : a+L ;  1-p_t = match? q : 1-q
//   loss = (t?0.25:0.75) * ce * (1-p_t)^2
// ---------------------------------------------------------------------------

#define MAX_NODES  262144
#define MAX_BLOCKS 256

__device__ __align__(16) unsigned short g_keys[MAX_NODES];
__device__ __align__(16) unsigned char  g_hash[MAX_NODES];
__device__ float g_part_es[MAX_BLOCKS];
__device__ int   g_part_ec[MAX_BLOCKS];
__device__ float g_part_ns[MAX_BLOCKS];
__device__ int   g_part_nc[MAX_BLOCKS];
__device__ unsigned int g_bar0;   // zero-initialized; reset by block 0 each run
__device__ unsigned int g_bar1;

__device__ __forceinline__ float focal_term(float x, bool t) {
    float a  = fabsf(x);
    float em = __expf(-a);                 // MUFU.EX2
    float w  = 1.0f + em;                  // w in [1,2]
    float L  = __logf(w);                  // MUFU.LG2
    float r  = fmaf(-0.5f, em, 0.9571f);   // ~1/w, err 4.3e-2
    r = r * fmaf(-w, r, 2.0f);             // Newton -> 1.8e-3
    r = r * fmaf(-w, r, 2.0f);             // Newton -> 3.4e-6
    float q  = em * r;                     // 1 - sigmoid(|x|)
    bool  m  = ((x >= 0.0f) == t);
    float omp = m ? q : (1.0f - q);        // 1 - p_t
    float ce  = m ? L : (a + L);           // BCE-with-logits
    float at  = t ? 0.25f : 0.75f;         // ALPHA=0.25
    return at * ce * omp * omp;            // GAMMA=2
}

// block reduction of (float, int) -> one slot per block
__device__ __forceinline__ void block_reduce_store(float s, int c,
                                                   float* ps, int* pc) {
    #pragma unroll
    for (int o = 16; o > 0; o >>= 1) {
        s += __shfl_down_sync(0xFFFFFFFFu, s, o);
        c += __shfl_down_sync(0xFFFFFFFFu, c, o);
    }
    __shared__ float sh_s[32];
    __shared__ int   sh_c[32];
    int lane = threadIdx.x & 31;
    int wid  = threadIdx.x >> 5;
    if (lane == 0) { sh_s[wid] = s; sh_c[wid] = c; }
    __syncthreads();
    int nw = (blockDim.x + 31) >> 5;
    if (wid == 0) {
        s = (lane < nw) ? sh_s[lane] : 0.0f;
        c = (lane < nw) ? sh_c[lane] : 0;
        #pragma unroll
        for (int o = 16; o > 0; o >>= 1) {
            s += __shfl_down_sync(0xFFFFFFFFu, s, o);
            c += __shfl_down_sync(0xFFFFFFFFu, c, o);
        }
        if (lane == 0) { ps[blockIdx.x] = s; pc[blockIdx.x] = c; }
    }
    __syncthreads();
}

__device__ __forceinline__ void grid_barrier(unsigned int* bar, int nb) {
    __syncthreads();
    if (threadIdx.x == 0) {
        __threadfence();
        atomicAdd(bar, 1u);
        while (*(volatile unsigned int*)bar < (unsigned int)nb) { }
    }
    __syncthreads();
    __threadfence();
}

__device__ __forceinline__ bool edge_target(const unsigned char* sh,
                                            int sidx, int didx) {
    unsigned int hs = sh[sidx];
    unsigned int hd = sh[didx];
    bool t = false;
    if ((hs == hd) & (hs != 0u)) {            // ~0.4% of edges
        t = (g_keys[sidx] == g_keys[didx]);   // rare exact LDGs
    }
    return t;
}

__global__ void __launch_bounds__(1024, 1)
fused_kernel(const float* __restrict__ edge_logits,
             const float* __restrict__ node_logits,
             const int*   __restrict__ batch,
             const int*   __restrict__ pinst,
             const int*   __restrict__ src,
             const int*   __restrict__ dst,
             int E, int N, int nvec,
             float* __restrict__ out) {
    extern __shared__ unsigned char sh[];
    int tid     = threadIdx.x;
    int nb      = gridDim.x;
    int gtid    = blockIdx.x * blockDim.x + tid;
    int gstride = nb * blockDim.x;

    // ---- phase 1: nodes (build key + hash tables, node loss/acc) ----
    float ns = 0.0f; int nc = 0;
    for (int i = gtid; i < N; i += gstride) {
        int p = pinst[i];
        int b = batch[i];
        unsigned short key = (p == 0) ? (unsigned short)0
                                      : (unsigned short)((b << 10) | p);
        g_keys[i] = key;
        g_hash[i] = (key == 0) ? (unsigned char)0
                               : (unsigned char)((key % 255) + 1);
        float x = node_logits[i];
        bool  t = (p != 0);
        ns += focal_term(x, t);
        nc += ((x > 0.0f) == t) ? 1 : 0;
    }
    block_reduce_store(ns, nc, g_part_ns, g_part_nc);

    grid_barrier(&g_bar0, nb);   // tables complete, visible in L2

    // ---- broadcast hash table into shared memory ----
    int nw4 = (N + 15) >> 4;
    const uint4* hv = (const uint4*)g_hash;
    uint4* s4 = (uint4*)sh;
    for (int i = tid; i < nw4; i += blockDim.x) s4[i] = hv[i];
    __syncthreads();

    // ---- phase 2: edges (vec4 streams + smem filter gathers) ----
    const float4* elv = (const float4*)edge_logits;
    const int4*   svp = (const int4*)src;
    const int4*   dvp = (const int4*)dst;
    float es = 0.0f; int ec = 0;
    for (int i = gtid; i < nvec; i += gstride) {
        float4 x  = __ldcs(&elv[i]);   // streaming; keep L1 for key lookups
        int4   sv = __ldcs(&svp[i]);
        int4   dv = __ldcs(&dvp[i]);

        bool t0 = edge_target(sh, sv.x, dv.x);
        bool t1 = edge_target(sh, sv.y, dv.y);
        bool t2 = edge_target(sh, sv.z, dv.z);
        bool t3 = edge_target(sh, sv.w, dv.w);

        es += focal_term(x.x, t0);
        es += focal_term(x.y, t1);
        es += focal_term(x.z, t2);
        es += focal_term(x.w, t3);

        ec += ((x.x > 0.0f) == t0) ? 1 : 0;
        ec += ((x.y > 0.0f) == t1) ? 1 : 0;
        ec += ((x.z > 0.0f) == t2) ? 1 : 0;
        ec += ((x.w > 0.0f) == t3) ? 1 : 0;
    }
    // tail edges (E % 4, or whole range if vec path disabled)
    if (blockIdx.x == 0 && tid == 0) {
        for (int e = nvec << 2; e < E; e++) {
            int sidx = src[e], didx = dst[e];
            unsigned short ks = g_keys[sidx], kd = g_keys[didx];
            bool t = (ks == kd) && (ks != 0);
            float x = edge_logits[e];
            es += focal_term(x, t);
            ec += ((x > 0.0f) == t) ? 1 : 0;
        }
    }
    block_reduce_store(es, ec, g_part_es, g_part_ec);

    // ---- final barrier; block 0 reduces partials and writes outputs ----
    if (tid == 0) { __threadfence(); atomicAdd(&g_bar1, 1u); }
    if (blockIdx.x != 0) return;
    if (tid == 0) {
        while (*(volatile unsigned int*)&g_bar1 < (unsigned int)nb) { }
    }
    __syncthreads();
    __threadfence();

    if (tid < 32) {
        double des = 0.0, dns = 0.0;
        int iec = 0, inc = 0;
        for (int i = tid; i < nb; i += 32) {
            des += (double)g_part_es[i];
            dns += (double)g_part_ns[i];
            iec += g_part_ec[i];
            inc += g_part_nc[i];
        }
        #pragma unroll
        for (int o = 16; o > 0; o >>= 1) {
            des += __shfl_down_sync(0xFFFFFFFFu, des, o);
            dns += __shfl_down_sync(0xFFFFFFFFu, dns, o);
            iec += __shfl_down_sync(0xFFFFFFFFu, iec, o);
            inc += __shfl_down_sync(0xFFFFFFFFu, inc, o);
        }
        if (tid == 0) {
            float edge_loss = (float)(des / (double)E);
            float node_loss = (float)(dns / (double)N);
            out[0] = edge_loss + node_loss;  // EDGE_W = NODE_W = 1
            out[1] = edge_loss;
            out[2] = node_loss;
            out[3] = (float)((double)iec / (double)E);
            out[4] = (float)((double)inc / (double)N);
            g_bar0 = 0;                      // reset for next graph replay
            g_bar1 = 0;
        }
    }
}

extern "C" void kernel_launch(void* const* d_in, const int* in_sizes, int n_in,
                              void* d_out, int out_size) {
    const float* edge_logits = (const float*)d_in[0];
    const float* node_logits = (const float*)d_in[1];
    const int*   batch       = (const int*)d_in[2];
    const int*   pinst       = (const int*)d_in[3];
    const int*   edge_index  = (const int*)d_in[4];

    int E = in_sizes[0];
    int N = in_sizes[1];
    const int* src = edge_index;
    const int* dst = edge_index + E;
    float* out = (float*)d_out;

    // vec4 path only if dst pointer stays 16B-aligned (E % 4 == 0)
    int nvec = ((E & 3) == 0) ? (E >> 2) : 0;

    int smem_bytes = (((N + 15) >> 4) << 4);   // hash table, 16B padded
    cudaFuncSetAttribute(fused_kernel,
                         cudaFuncAttributeMaxDynamicSharedMemorySize,
                         smem_bytes);

    int sm_count = 148;
    cudaDeviceGetAttribute(&sm_count, cudaDevAttrMultiProcessorCount, 0);
    int nblocks = (sm_count < MAX_BLOCKS) ? sm_count : MAX_BLOCKS;

    fused_kernel<<<nblocks, 1024, smem_bytes>>>(edge_logits, node_logits,
                                                batch, pinst, src, dst,
                                                E, N, nvec, out);
}